// round 5
// baseline (speedup 1.0000x reference)
#include <cuda_runtime.h>
#include <math_constants.h>
#include <cstdint>

// ---------------- problem constants ----------------
#define BATCHSZ 4096
#define DIM     256
#define NROWS   8192
#define SIMSCALE 2.0f          // 1 / temperature
#define NCHUNKS 2              // column halves (h_i | h_j)

// ---------------- device scratch (no allocs allowed) ----------------
__device__ float g_pm[NCHUNKS][NROWS];
__device__ float g_ps[NCHUNKS][NROWS];
__device__ float g_lrow[NROWS];

// ---------------- smem layout (floats) ----------------
// A' fragment-major: [t16 0..7][ks 0..31][lane 0..31][4 regs] + 4 pad / (t16,ks)
// B' fragment-major (per 32-K chunk, double buffered):
//   [nt8 0..15][kq 0..3][lane 0..31][2 regs] + 2 pad / (nt,kq)
#define A_OFF   0
#define A_FLTS  (8 * 32 * 132)          // 33792
#define B_OFF   A_FLTS
#define B_BUF   (16 * 4 * 66)           // 4224 floats per buffer
#define RED_OFF (B_OFF + 2 * B_BUF)     // 42240: [4 wn][128 rows][m,s]
#define SMEM_FLOATS (RED_OFF + 1024)    // 43264
#define SMEM_BYTES  (SMEM_FLOATS * 4)   // 173056

// ---------------- helpers ----------------
static __device__ __forceinline__ uint32_t f2tf32(float x) {
    uint32_t y;
    asm("cvt.rna.tf32.f32 %0, %1;" : "=r"(y) : "f"(x));   // round-nearest: unbiased
    return y;
}
static __device__ __forceinline__ void mma_tf32(float c[4],
        uint32_t a0, uint32_t a1, uint32_t a2, uint32_t a3,
        uint32_t b0, uint32_t b1) {
    asm volatile(
        "mma.sync.aligned.m16n8k8.row.col.f32.tf32.tf32.f32 "
        "{%0,%1,%2,%3}, {%4,%5,%6,%7}, {%8,%9}, {%0,%1,%2,%3};"
        : "+f"(c[0]), "+f"(c[1]), "+f"(c[2]), "+f"(c[3])
        : "r"(a0), "r"(a1), "r"(a2), "r"(a3), "r"(b0), "r"(b1));
}

// ==========================================================================
// Fused tf32 mma.sync GEMM + online logsumexp, fragment-major smem.
// CTA = (row tile rt: 128 rows, A resident) x (column half ch: 4096 cols).
// 16 warps (4 per SMSP for latency hiding), warp grid 4m x 4n, warp tile
// 32x32 (m16n8k8 tf32, acc 2x4x4). 256 K-chunks, B double-buffered via
// LDG-prefetch + STS.
// ==========================================================================
__global__ __launch_bounds__(512, 1)
void ntxent_mma_kernel(const float* __restrict__ hi, const float* __restrict__ hj) {
    extern __shared__ float smf[];
    uint32_t* smu = (uint32_t*)smf;
    const int tid = threadIdx.x;
    const int w = tid >> 5, lane = tid & 31;
    const int g = lane >> 2, tq = lane & 3;     // quad layout for mma frags
    const int wm = w >> 2, wn = w & 3;          // warp grid 4 x 4

    const int rt = blockIdx.x & 63;
    const int ch = blockIdx.x >> 6;
    const int r0 = rt * 128;
    const float* arow = (rt < 32) ? hi + (size_t)rt * 128 * DIM
                                  : hj + (size_t)(rt - 32) * 128 * DIM;
    const float* bsrc = ch ? hj : hi;

    // Per-chunk B ownership: 2 float4 per thread (512 threads x 2 = 1024).
    const int pn[2] = { (0 * 512 + tid) >> 3, (1 * 512 + tid) >> 3 };
    const int pk = (tid & 7) * 4;
    uint32_t pb[2];
#pragma unroll
    for (int i = 0; i < 2; i++)
        pb[i] = (uint32_t)(((pn[i] >> 3) * 4 + (pk >> 3)) * 66
                           + (pn[i] & 7) * 8 + ((pk >> 2) & 1));

    // -------- prologue: LDG chunk 0 --------
    float4 pf[2];
#pragma unroll
    for (int i = 0; i < 2; i++)
        pf[i] = *(const float4*)(bsrc + (size_t)pn[i] * DIM + pk);

    // -------- A tile -> fragment-major smem (tf32) --------
#pragma unroll
    for (int i = 0; i < 16; i++) {
        int f = i * 512 + tid;
        int r = f >> 6, k = (f & 63) << 2;
        float4 v = *(const float4*)(arow + (size_t)r * DIM + k);
        uint32_t o = (uint32_t)(((r >> 4) * 32 + (k >> 3)) * 132 + (r & 7) * 16
                                + ((r >> 3) & 1) + 2 * ((k >> 2) & 1));
        smu[o + 0]  = f2tf32(v.x);
        smu[o + 4]  = f2tf32(v.y);
        smu[o + 8]  = f2tf32(v.z);
        smu[o + 12] = f2tf32(v.w);
    }

    // -------- STS chunk 0 -> buffer 0 --------
    {
        uint32_t* d = smu + B_OFF;
#pragma unroll
        for (int i = 0; i < 2; i++) {
            d[pb[i] + 0] = f2tf32(pf[i].x);
            d[pb[i] + 2] = f2tf32(pf[i].y);
            d[pb[i] + 4] = f2tf32(pf[i].z);
            d[pb[i] + 6] = f2tf32(pf[i].w);
        }
    }
    __syncthreads();

    float acc[2][4][4];
#pragma unroll
    for (int mf = 0; mf < 2; mf++)
#pragma unroll
        for (int nf = 0; nf < 4; nf++)
#pragma unroll
            for (int c = 0; c < 4; c++) acc[mf][nf][c] = 0.f;

    float runM = -CUDART_INF_F, runS = 0.f;

    for (int t = 0; t < 32; t++) {
        for (int kc = 0; kc < 8; kc++) {
            const int gc = t * 8 + kc;
            const int buf = gc & 1;

            if (gc < 255) {                     // prefetch chunk gc+1 to regs
                const int t1 = (gc + 1) >> 3, kc1 = (gc + 1) & 7;
                const float* base = bsrc + (size_t)(t1 * 128) * DIM + kc1 * 32;
#pragma unroll
                for (int i = 0; i < 2; i++)
                    pf[i] = *(const float4*)(base + (size_t)pn[i] * DIM + pk);
            }

            // -------- MMA: 4 k8-steps, vector fragment loads --------
            const uint32_t* Bu = smu + B_OFF + buf * B_BUF;
#pragma unroll
            for (int kq = 0; kq < 4; kq++) {
                uint2 bfr[4];
#pragma unroll
                for (int nf = 0; nf < 4; nf++)
                    bfr[nf] = *(const uint2*)(Bu + ((wn * 4 + nf) * 4 + kq) * 66
                                              + lane * 2);
#pragma unroll
                for (int mf = 0; mf < 2; mf++) {
                    uint4 af = *(const uint4*)(smu
                        + ((wm * 2 + mf) * 32 + (kc * 4 + kq)) * 132 + lane * 4);
#pragma unroll
                    for (int nf = 0; nf < 4; nf++)
                        mma_tf32(acc[mf][nf], af.x, af.y, af.z, af.w,
                                 bfr[nf].x, bfr[nf].y);
                }
            }

            if (gc < 255) {                     // STS chunk gc+1 -> other buffer
                uint32_t* d = smu + B_OFF + (buf ^ 1) * B_BUF;
#pragma unroll
                for (int i = 0; i < 2; i++) {
                    d[pb[i] + 0] = f2tf32(pf[i].x);
                    d[pb[i] + 2] = f2tf32(pf[i].y);
                    d[pb[i] + 4] = f2tf32(pf[i].z);
                    d[pb[i] + 6] = f2tf32(pf[i].w);
                }
            }
            __syncthreads();
        }

        // -------- epilogue: fold 128-col sim tile into online (m, s) --------
        {
            const int c0g = ch * 4096 + t * 128 + wn * 32 + tq * 2;
            float* red = smf + RED_OFF;         // [wn][row][m,s]
            float tm[4], ts[4];
#pragma unroll
            for (int mf = 0; mf < 2; mf++)
#pragma unroll
                for (int hh = 0; hh < 2; hh++) {
                    const int gr = r0 + wm * 32 + mf * 16 + g + hh * 8;
                    float m = -CUDART_INF_F;
#pragma unroll
                    for (int nf = 0; nf < 4; nf++)
#pragma unroll
                        for (int c = 0; c < 2; c++) {
                            float v = acc[mf][nf][hh * 2 + c] * SIMSCALE;
                            if (gr == c0g + nf * 8 + c) v = -CUDART_INF_F;  // self mask
                            acc[mf][nf][hh * 2 + c] = v;
                            m = fmaxf(m, v);
                        }
                    tm[mf * 2 + hh] = m;
                }
#pragma unroll
            for (int s = 0; s < 4; s++) {       // quad reduce (lanes of same row)
                tm[s] = fmaxf(tm[s], __shfl_xor_sync(0xffffffffu, tm[s], 1));
                tm[s] = fmaxf(tm[s], __shfl_xor_sync(0xffffffffu, tm[s], 2));
            }
#pragma unroll
            for (int mf = 0; mf < 2; mf++)
#pragma unroll
                for (int hh = 0; hh < 2; hh++) {
                    float sv = 0.f;
#pragma unroll
                    for (int nf = 0; nf < 4; nf++)
#pragma unroll
                        for (int c = 0; c < 2; c++)
                            sv += __expf(acc[mf][nf][hh * 2 + c] - tm[mf * 2 + hh]);
                    ts[mf * 2 + hh] = sv;
                }
#pragma unroll
            for (int s = 0; s < 4; s++) {
                ts[s] += __shfl_xor_sync(0xffffffffu, ts[s], 1);
                ts[s] += __shfl_xor_sync(0xffffffffu, ts[s], 2);
            }
            if (tq == 0) {
#pragma unroll
                for (int mf = 0; mf < 2; mf++)
#pragma unroll
                    for (int hh = 0; hh < 2; hh++) {
                        int row = wm * 32 + mf * 16 + g + hh * 8;
                        red[(wn * 128 + row) * 2 + 0] = tm[mf * 2 + hh];
                        red[(wn * 128 + row) * 2 + 1] = ts[mf * 2 + hh];
                    }
            }
            __syncthreads();
            if (tid < 128) {                    // thread tid owns row r0+tid
                float M = red[tid * 2];
#pragma unroll
                for (int q = 1; q < 4; q++) M = fmaxf(M, red[(q * 128 + tid) * 2]);
                float S = 0.f;
#pragma unroll
                for (int q = 0; q < 4; q++)
                    S += red[(q * 128 + tid) * 2 + 1]
                       * __expf(red[(q * 128 + tid) * 2] - M);
                float nm = fmaxf(runM, M);
                runS = runS * __expf(runM - nm) + S * __expf(M - nm);
                runM = nm;
            }
            __syncthreads();                    // red reads done before next tile
#pragma unroll
            for (int mf = 0; mf < 2; mf++)
#pragma unroll
                for (int nf = 0; nf < 4; nf++)
#pragma unroll
                    for (int c = 0; c < 4; c++) acc[mf][nf][c] = 0.f;
        }
    }

    if (tid < 128) {
        g_pm[ch][r0 + tid] = runM;
        g_ps[ch][r0 + tid] = runS;
    }
}

// ==========================================================================
// Merge 2 column-half partials per row, compute pos_i (exact fp32), per-row loss.
// ==========================================================================
__global__ void combine_kernel(const float* __restrict__ hi, const float* __restrict__ hj) {
    const int gwarp = (int)((blockIdx.x * blockDim.x + threadIdx.x) >> 5);
    const int lane = threadIdx.x & 31;
    if (gwarp >= BATCHSZ) return;

    const float* a = hi + (size_t)gwarp * DIM;
    const float* b = hj + (size_t)gwarp * DIM;
    const int k = lane * 8;
    float4 a0 = *(const float4*)(a + k);
    float4 a1 = *(const float4*)(a + k + 4);
    float4 b0 = *(const float4*)(b + k);
    float4 b1 = *(const float4*)(b + k + 4);
    float d = a0.x * b0.x + a0.y * b0.y + a0.z * b0.z + a0.w * b0.w
            + a1.x * b1.x + a1.y * b1.y + a1.z * b1.z + a1.w * b1.w;
#pragma unroll
    for (int off = 16; off > 0; off >>= 1)
        d += __shfl_xor_sync(0xffffffffu, d, off);
    const float pos = d * SIMSCALE;

    if (lane < 2) {
        const int r = gwarp + lane * BATCHSZ;
        float m0 = g_pm[0][r], m1 = g_pm[1][r];
        float M = fmaxf(m0, m1);
        float S = g_ps[0][r] * __expf(m0 - M) + g_ps[1][r] * __expf(m1 - M);
        g_lrow[r] = M + logf(S) - pos;
    }
}

// Deterministic single-block reduction -> mean (replay-stable, no atomics).
__global__ void reduce_kernel(float* __restrict__ out) {
    __shared__ float sm[256];
    const int tid = threadIdx.x;
    float s = 0.f;
    for (int i = tid; i < NROWS; i += 256) s += g_lrow[i];
    sm[tid] = s;
    __syncthreads();
    for (int stride = 128; stride > 0; stride >>= 1) {
        if (tid < stride) sm[tid] += sm[tid + stride];
        __syncthreads();
    }
    if (tid == 0) out[0] = sm[0] * (1.0f / NROWS);
}

extern "C" void kernel_launch(void* const* d_in, const int* in_sizes, int n_in,
                              void* d_out, int out_size) {
    const float* hi = (const float*)d_in[0];
    const float* hj = (const float*)d_in[1];
    float* out = (float*)d_out;

    cudaFuncSetAttribute(ntxent_mma_kernel,
                         cudaFuncAttributeMaxDynamicSharedMemorySize, SMEM_BYTES);
    ntxent_mma_kernel<<<128, 512, SMEM_BYTES>>>(hi, hj);
    combine_kernel<<<(BATCHSZ * 32) / 256, 256>>>(hi, hj);
    reduce_kernel<<<1, 256>>>(out);
}

// round 7
// speedup vs baseline: 2.5145x; 2.5145x over previous
#include <cuda_runtime.h>
#include <math_constants.h>
#include <cstdint>

// ---------------- problem constants ----------------
#define BATCHSZ 4096
#define DIM     256
#define NROWS   8192
#define SIMSCALE 2.0f          // 1 / temperature
#define NCHUNKS 2              // column halves (h_i | h_j)

// ---------------- device scratch (no allocs allowed) ----------------
__device__ float g_pm[NCHUNKS][NROWS];
__device__ float g_ps[NCHUNKS][NROWS];
__device__ float g_lrow[NROWS];

// ---------------- smem layout (u32 words) ----------------
// A' fragment-major bf16: [t16 0..7][ks16 0..15][lane][4 regs] + 4 pad
//   AF(t16,ks,lane,reg) = (t16*16+ks)*132 + lane*4 + reg
//   reg order = {a0,a1,a2,a3} of m16n8k16 (a0=(g,2tq),a1=(g+8,2tq),
//   a2=(g,2tq+8),a3=(g+8,2tq+8)); each u32 = 2 packed bf16 (lo = even k).
// B' fragment-major bf16 (per 32-K chunk = 2 ks16 steps, double buffered):
//   [nt8 0..15][ks 0..1][lane][2 regs] + 2 pad
//   BF(nt,ks,lane,reg) = (nt*2+ks)*66 + lane*2 + reg  (reg = {b0,b1})
#define A_U32   (8 * 16 * 132)          // 16896
#define B_OFF   A_U32
#define B_BUF   (16 * 2 * 66)           // 2112 u32 per buffer
#define RED_OFF (B_OFF + 2 * B_BUF)     // 21120: [4 wn][128 rows][m,s]
#define SMEM_U32 (RED_OFF + 1024)       // 22144
#define SMEM_BYTES (SMEM_U32 * 4)       // 88576

// ---------------- helpers ----------------
static __device__ __forceinline__ uint32_t f2bf2(float lo, float hi) {
    uint32_t r;   // d = {hi=a, lo=b}
    asm("cvt.rn.bf16x2.f32 %0, %1, %2;" : "=r"(r) : "f"(hi), "f"(lo));
    return r;
}
static __device__ __forceinline__ void mma_bf16(float c[4],
        uint32_t a0, uint32_t a1, uint32_t a2, uint32_t a3,
        uint32_t b0, uint32_t b1) {
    asm volatile(
        "mma.sync.aligned.m16n8k16.row.col.f32.bf16.bf16.f32 "
        "{%0,%1,%2,%3}, {%4,%5,%6,%7}, {%8,%9}, {%0,%1,%2,%3};"
        : "+f"(c[0]), "+f"(c[1]), "+f"(c[2]), "+f"(c[3])
        : "r"(a0), "r"(a1), "r"(a2), "r"(a3), "r"(b0), "r"(b1));
}

// ==========================================================================
// Fused bf16 mma.sync GEMM + online logsumexp, fragment-major smem.
// CTA = (row tile rt: 128 rows, A resident) x (column half ch: 4096 cols).
// 8 warps, warp grid 2m x 4n, warp tile 64x32, m16n8k16 bf16 (f32 accum).
// 256 K-chunks (32 tiles x 8), B double-buffered via LDG-prefetch + STS.
// ==========================================================================
__global__ __launch_bounds__(256, 1)
void ntxent_mma_kernel(const float* __restrict__ hi, const float* __restrict__ hj) {
    extern __shared__ float smf[];
    uint32_t* smu = (uint32_t*)smf;
    const int tid = threadIdx.x;
    const int w = tid >> 5, lane = tid & 31;
    const int g = lane >> 2, tq = lane & 3;     // quad layout for mma frags
    const int wm = w >> 2, wn = w & 3;          // warp grid 2 x 4

    const int rt = blockIdx.x & 63;
    const int ch = blockIdx.x >> 6;
    const int r0 = rt * 128;
    const float* arow = (rt < 32) ? hi + (size_t)rt * 128 * DIM
                                  : hj + (size_t)(rt - 32) * 128 * DIM;
    const float* bsrc = ch ? hj : hi;

    // Per-chunk B ownership: 4 float4 per thread (256 x 4 x 4 = 128 rows x 32 K).
    // f = i*256+tid -> n = f>>3 (col row 0..127), kk = (f&7)*4 (chunk-local k).
    const int pn[4] = { (0 * 256 + tid) >> 3, (1 * 256 + tid) >> 3,
                        (2 * 256 + tid) >> 3, (3 * 256 + tid) >> 3 };
    const int pk = (tid & 7) * 4;               // same for all i (256 % 8 == 0)
    // Two u32 fragment-store slots per float4 (pairs p0 and p0+1).
    uint32_t pb0[4], pb1[4];
#pragma unroll
    for (int i = 0; i < 4; i++) {
        const int nt = pn[i] >> 3, gg = pn[i] & 7;
        const int ks = pk >> 4, p0 = (pk & 15) >> 1;
        const uint32_t base = (uint32_t)((nt * 2 + ks) * 66);
        pb0[i] = base + (gg * 4 + (p0 & 3)) * 2 + (p0 >> 2);
        pb1[i] = base + (gg * 4 + ((p0 + 1) & 3)) * 2 + ((p0 + 1) >> 2);
    }

    // -------- prologue: LDG chunk 0 --------
    float4 pf[4];
#pragma unroll
    for (int i = 0; i < 4; i++)
        pf[i] = *(const float4*)(bsrc + (size_t)pn[i] * DIM + pk);

    // -------- A tile -> fragment-major bf16 smem --------
#pragma unroll
    for (int i = 0; i < 16; i++) {
        int f = i * 256 + tid;                  // float4 slot 0..4095
        int r = f >> 5, k = (f & 31) << 3;      // 8 floats per thread-slot
        float4 v0 = *(const float4*)(arow + (size_t)r * DIM + k);
        float4 v1 = *(const float4*)(arow + (size_t)r * DIM + k + 4);
        const int t16 = r >> 4, rr = r & 15, ga = rr & 7, h8 = rr >> 3;
        const int ks = k >> 4, p0 = (k & 15) >> 1;   // p0 in {0, 4} (k mult of 8)
        const uint32_t base = (uint32_t)((t16 * 16 + ks) * 132);
        uint32_t w0 = f2bf2(v0.x, v0.y), w1 = f2bf2(v0.z, v0.w);
        uint32_t w2 = f2bf2(v1.x, v1.y), w3 = f2bf2(v1.z, v1.w);
        const int rk = p0 >> 2;                 // 0 -> a0/a1 slots, 1 -> a2/a3
        smu[base + (ga * 4 + ((p0 + 0) & 3)) * 4 + h8 + 2 * rk] = w0;
        smu[base + (ga * 4 + ((p0 + 1) & 3)) * 4 + h8 + 2 * rk] = w1;
        smu[base + (ga * 4 + ((p0 + 2) & 3)) * 4 + h8 + 2 * rk] = w2;
        smu[base + (ga * 4 + ((p0 + 3) & 3)) * 4 + h8 + 2 * rk] = w3;
    }

    // -------- STS chunk 0 -> buffer 0 --------
    {
        uint32_t* d = smu + B_OFF;
#pragma unroll
        for (int i = 0; i < 4; i++) {
            d[pb0[i]] = f2bf2(pf[i].x, pf[i].y);
            d[pb1[i]] = f2bf2(pf[i].z, pf[i].w);
        }
    }
    __syncthreads();

    float acc[4][4][4];
#pragma unroll
    for (int mf = 0; mf < 4; mf++)
#pragma unroll
        for (int nf = 0; nf < 4; nf++)
#pragma unroll
            for (int c = 0; c < 4; c++) acc[mf][nf][c] = 0.f;

    float runM = -CUDART_INF_F, runS = 0.f;

    for (int t = 0; t < 32; t++) {
        for (int kc = 0; kc < 8; kc++) {
            const int gc = t * 8 + kc;
            const int buf = gc & 1;

            if (gc < 255) {                     // prefetch chunk gc+1 to regs
                const int t1 = (gc + 1) >> 3, kc1 = (gc + 1) & 7;
                const float* base = bsrc + (size_t)(t1 * 128) * DIM + kc1 * 32;
#pragma unroll
                for (int i = 0; i < 4; i++)
                    pf[i] = *(const float4*)(base + (size_t)pn[i] * DIM + pk);
            }

            // -------- MMA: 2 k16-steps, vector fragment loads --------
            const uint32_t* Bu = smu + B_OFF + buf * B_BUF;
#pragma unroll
            for (int ksl = 0; ksl < 2; ksl++) {
                uint2 bfr[4];
#pragma unroll
                for (int nf = 0; nf < 4; nf++)
                    bfr[nf] = *(const uint2*)(Bu + ((wn * 4 + nf) * 2 + ksl) * 66
                                              + lane * 2);
#pragma unroll
                for (int mf = 0; mf < 4; mf++) {
                    uint4 af = *(const uint4*)(smu
                        + ((wm * 4 + mf) * 16 + (kc * 2 + ksl)) * 132 + lane * 4);
#pragma unroll
                    for (int nf = 0; nf < 4; nf++)
                        mma_bf16(acc[mf][nf], af.x, af.y, af.z, af.w,
                                 bfr[nf].x, bfr[nf].y);
                }
            }

            if (gc < 255) {                     // STS chunk gc+1 -> other buffer
                uint32_t* d = smu + B_OFF + (buf ^ 1) * B_BUF;
#pragma unroll
                for (int i = 0; i < 4; i++) {
                    d[pb0[i]] = f2bf2(pf[i].x, pf[i].y);
                    d[pb1[i]] = f2bf2(pf[i].z, pf[i].w);
                }
            }
            __syncthreads();
        }

        // -------- epilogue: fold 128-col sim tile into online (m, s) --------
        {
            const int c0g = ch * 4096 + t * 128 + wn * 32 + tq * 2;
            float* red = smf + RED_OFF;         // [wn][row][m,s]
            float tm[8], ts[8];
#pragma unroll
            for (int mf = 0; mf < 4; mf++)
#pragma unroll
                for (int hh = 0; hh < 2; hh++) {
                    const int gr = r0 + wm * 64 + mf * 16 + g + hh * 8;
                    float m = -CUDART_INF_F;
#pragma unroll
                    for (int nf = 0; nf < 4; nf++)
#pragma unroll
                        for (int c = 0; c < 2; c++) {
                            float v = acc[mf][nf][hh * 2 + c] * SIMSCALE;
                            if (gr == c0g + nf * 8 + c) v = -CUDART_INF_F;  // self mask
                            acc[mf][nf][hh * 2 + c] = v;
                            m = fmaxf(m, v);
                        }
                    tm[mf * 2 + hh] = m;
                }
#pragma unroll
            for (int s = 0; s < 8; s++) {       // quad reduce (lanes of same row)
                tm[s] = fmaxf(tm[s], __shfl_xor_sync(0xffffffffu, tm[s], 1));
                tm[s] = fmaxf(tm[s], __shfl_xor_sync(0xffffffffu, tm[s], 2));
            }
#pragma unroll
            for (int mf = 0; mf < 4; mf++)
#pragma unroll
                for (int hh = 0; hh < 2; hh++) {
                    float sv = 0.f;
#pragma unroll
                    for (int nf = 0; nf < 4; nf++)
#pragma unroll
                        for (int c = 0; c < 2; c++)
                            sv += __expf(acc[mf][nf][hh * 2 + c] - tm[mf * 2 + hh]);
                    ts[mf * 2 + hh] = sv;
                }
#pragma unroll
            for (int s = 0; s < 8; s++) {
                ts[s] += __shfl_xor_sync(0xffffffffu, ts[s], 1);
                ts[s] += __shfl_xor_sync(0xffffffffu, ts[s], 2);
            }
            if (tq == 0) {
#pragma unroll
                for (int mf = 0; mf < 4; mf++)
#pragma unroll
                    for (int hh = 0; hh < 2; hh++) {
                        int row = wm * 64 + mf * 16 + g + hh * 8;
                        red[(wn * 128 + row) * 2 + 0] = tm[mf * 2 + hh];
                        red[(wn * 128 + row) * 2 + 1] = ts[mf * 2 + hh];
                    }
            }
            __syncthreads();
            if (tid < 128) {                    // thread tid owns row r0+tid
                float M = red[tid * 2];
#pragma unroll
                for (int q = 1; q < 4; q++) M = fmaxf(M, red[(q * 128 + tid) * 2]);
                float S = 0.f;
#pragma unroll
                for (int q = 0; q < 4; q++)
                    S += red[(q * 128 + tid) * 2 + 1]
                       * __expf(red[(q * 128 + tid) * 2] - M);
                float nm = fmaxf(runM, M);
                runS = runS * __expf(runM - nm) + S * __expf(M - nm);
                runM = nm;
            }
            __syncthreads();                    // red reads done before next tile
#pragma unroll
            for (int mf = 0; mf < 4; mf++)
#pragma unroll
                for (int nf = 0; nf < 4; nf++)
#pragma unroll
                    for (int c = 0; c < 4; c++) acc[mf][nf][c] = 0.f;
        }
    }

    if (tid < 128) {
        g_pm[ch][r0 + tid] = runM;
        g_ps[ch][r0 + tid] = runS;
    }
}

// ==========================================================================
// Merge 2 column-half partials per row, compute pos_i (exact fp32), per-row loss.
// ==========================================================================
__global__ void combine_kernel(const float* __restrict__ hi, const float* __restrict__ hj) {
    const int gwarp = (int)((blockIdx.x * blockDim.x + threadIdx.x) >> 5);
    const int lane = threadIdx.x & 31;
    if (gwarp >= BATCHSZ) return;

    const float* a = hi + (size_t)gwarp * DIM;
    const float* b = hj + (size_t)gwarp * DIM;
    const int k = lane * 8;
    float4 a0 = *(const float4*)(a + k);
    float4 a1 = *(const float4*)(a + k + 4);
    float4 b0 = *(const float4*)(b + k);
    float4 b1 = *(const float4*)(b + k + 4);
    float d = a0.x * b0.x + a0.y * b0.y + a0.z * b0.z + a0.w * b0.w
            + a1.x * b1.x + a1.y * b1.y + a1.z * b1.z + a1.w * b1.w;
#pragma unroll
    for (int off = 16; off > 0; off >>= 1)
        d += __shfl_xor_sync(0xffffffffu, d, off);
    const float pos = d * SIMSCALE;

    if (lane < 2) {
        const int r = gwarp + lane * BATCHSZ;
        float m0 = g_pm[0][r], m1 = g_pm[1][r];
        float M = fmaxf(m0, m1);
        float S = g_ps[0][r] * __expf(m0 - M) + g_ps[1][r] * __expf(m1 - M);
        g_lrow[r] = M + logf(S) - pos;
    }
}

// Deterministic single-block reduction -> mean (replay-stable, no atomics).
__global__ void reduce_kernel(float* __restrict__ out) {
    __shared__ float sm[256];
    const int tid = threadIdx.x;
    float s = 0.f;
    for (int i = tid; i < NROWS; i += 256) s += g_lrow[i];
    sm[tid] = s;
    __syncthreads();
    for (int stride = 128; stride > 0; stride >>= 1) {
        if (tid < stride) sm[tid] += sm[tid + stride];
        __syncthreads();
    }
    if (tid == 0) out[0] = sm[0] * (1.0f / NROWS);
}

extern "C" void kernel_launch(void* const* d_in, const int* in_sizes, int n_in,
                              void* d_out, int out_size) {
    const float* hi = (const float*)d_in[0];
    const float* hj = (const float*)d_in[1];
    float* out = (float*)d_out;

    cudaFuncSetAttribute(ntxent_mma_kernel,
                         cudaFuncAttributeMaxDynamicSharedMemorySize, SMEM_BYTES);
    ntxent_mma_kernel<<<128, 256, SMEM_BYTES>>>(hi, hj);
    combine_kernel<<<(BATCHSZ * 32) / 256, 256>>>(hi, hj);
    reduce_kernel<<<1, 256>>>(out);
}

// round 8
// speedup vs baseline: 3.7576x; 1.4944x over previous
#include <cuda_runtime.h>
#include <math_constants.h>
#include <cstdint>

// ---------------- problem constants ----------------
#define BATCHSZ 4096
#define DIM     256
#define NROWS   8192
#define NCH     4               // column chunks (2048 cols each)
#define TPC     16              // tiles per CTA (2048 / 128)
#define NKC     8               // 32-K chunks per tile
#define NCHUNKT (TPC * NKC)     // 128 chunks per CTA
// prescale = sqrt(2 * log2(e)): product of two prescaled values = sim * 2 * log2e
#define PRESCALE 1.6986436f
#define LN2F     0.69314718055994531f

// ---------------- device scratch (no allocs allowed) ----------------
__device__ uint32_t g_afrag[64 * 16384];        // [rt][t16][ks][lane][4reg] 4MB
__device__ uint32_t g_bfrag[64 * 8 * 2048];     // [ct][kc][nt][ks][lane][2reg] 4MB
__device__ float g_pm[NCH][NROWS];
__device__ float g_ps[NCH][NROWS];
__device__ float g_lrow[NROWS];

// ---------------- smem layout (u32 words) ----------------
#define A_U32    16384                  // A tile fragments (64KB)
#define B_OFF    16384                  // 3 chunk buffers x 2048 u32 (8KB each)
#define B_BUF    2048
#define RED_OFF  (B_OFF + 3 * B_BUF)    // 22528: [4 wn][128 rows][m,s] floats
#define SMEM_U32 (RED_OFF + 1024)       // 23552
#define SMEM_BYTES (SMEM_U32 * 4)       // 94208

// ---------------- helpers ----------------
static __device__ __forceinline__ uint32_t f2bf2(float lo, float hi) {
    uint32_t r;   // d = {hi, lo}
    asm("cvt.rn.bf16x2.f32 %0, %1, %2;" : "=r"(r) : "f"(hi), "f"(lo));
    return r;
}
static __device__ __forceinline__ float ex2f(float x) {
    float y;
    asm("ex2.approx.ftz.f32 %0, %1;" : "=f"(y) : "f"(x));
    return y;
}
static __device__ __forceinline__ uint32_t smem_u32(const void* p) {
    uint32_t a;
    asm("{ .reg .u64 t; cvta.to.shared.u64 t, %1; cvt.u32.u64 %0, t; }" : "=r"(a) : "l"(p));
    return a;
}
static __device__ __forceinline__ void mma_bf16(float c[4],
        uint32_t a0, uint32_t a1, uint32_t a2, uint32_t a3,
        uint32_t b0, uint32_t b1) {
    asm volatile(
        "mma.sync.aligned.m16n8k16.row.col.f32.bf16.bf16.f32 "
        "{%0,%1,%2,%3}, {%4,%5,%6,%7}, {%8,%9}, {%0,%1,%2,%3};"
        : "+f"(c[0]), "+f"(c[1]), "+f"(c[2]), "+f"(c[3])
        : "r"(a0), "r"(a1), "r"(a2), "r"(a3), "r"(b0), "r"(b1));
}
#define CP_ASYNC16(dst, src) \
    asm volatile("cp.async.cg.shared.global [%0], [%1], 16;" :: "r"(dst), "l"(src))
#define CP_COMMIT() asm volatile("cp.async.commit_group;" ::: "memory")
#define CP_WAIT(n)  asm volatile("cp.async.wait_group %0;" :: "n"(n) : "memory")

static __device__ __forceinline__ const float* srow(const float* hi, const float* hj, int r) {
    return (r < BATCHSZ) ? (hi + (size_t)r * DIM) : (hj + (size_t)(r - BATCHSZ) * DIM);
}

// ==========================================================================
// Pre-pass: convert inputs to pre-scaled bf16 fragment-major layouts.
// Blocks [0,1024): g_afrag. Blocks [1024,2048): g_bfrag. 4 u32 per thread.
// ==========================================================================
__global__ void prep_kernel(const float* __restrict__ hi, const float* __restrict__ hj) {
    const int tid = threadIdx.x;
    if (blockIdx.x < 1024) {
        // afrag: ai = rt<<14 | t16<<11 | ks<<7 | lane<<2 | reg
        const int ai = blockIdx.x * 1024 + tid * 4;
        const int rt = ai >> 14, rem = ai & 16383;
        const int t16 = rem >> 11, ks = (rem >> 7) & 15, l = (rem >> 2) & 31;
        const int g = l >> 2, tq = l & 3;
        const int row0 = rt * 128 + t16 * 16 + g;
        const int kb = ks * 16 + tq * 2;
#pragma unroll
        for (int reg = 0; reg < 4; reg++) {
            const int row = row0 + (reg & 1) * 8;
            const int k = kb + (reg >> 1) * 8;
            const float2 v = *(const float2*)(srow(hi, hj, row) + k);
            g_afrag[ai + reg] = f2bf2(v.x * PRESCALE, v.y * PRESCALE);
        }
    } else {
        // bfrag: bi = ct<<14 | kc<<11 | nt<<7 | ks<<6 | lane<<1 | reg
        const int b0 = (blockIdx.x - 1024) * 1024 + tid * 4;
#pragma unroll
        for (int j = 0; j < 4; j++) {
            const int bi = b0 + j;
            const int ct = bi >> 14, rem = bi & 16383;
            const int kc = rem >> 11, nt = (rem >> 7) & 15;
            const int ks = (rem >> 6) & 1, l = (rem >> 1) & 31, reg = bi & 1;
            const int col = ct * 128 + nt * 8 + (l >> 2);
            const int k = kc * 32 + ks * 16 + (l & 3) * 2 + reg * 8;
            const float2 v = *(const float2*)(srow(hi, hj, col) + k);
            g_bfrag[bi] = f2bf2(v.x * PRESCALE, v.y * PRESCALE);
        }
    }
}

// ==========================================================================
// Fused bf16 mma.sync GEMM + online logsumexp (base-2), cp.async pipeline.
// CTA = (row tile rt: 128 rows, A resident) x (column chunk ch: 2048 cols).
// 8 warps, warp grid 2m x 4n, warp tile 64x32, m16n8k16 bf16 (f32 accum).
// 3-deep 32-K chunk pipeline; 2 CTAs/SM so one CTA's MUFU epilogue overlaps
// the other's HMMA mainloop.
// ==========================================================================
__global__ __launch_bounds__(256, 2)
void ntxent_mma_kernel() {
    extern __shared__ float smf[];
    uint32_t* smu = (uint32_t*)smf;
    const uint32_t sbase = smem_u32(smf);
    const int tid = threadIdx.x;
    const int w = tid >> 5, lane = tid & 31;
    const int g = lane >> 2, tq = lane & 3;
    const int wm = w >> 2, wn = w & 3;          // warp grid 2 x 4

    const int rt = blockIdx.x & 63;
    const int ch = blockIdx.x >> 6;
    const int r0 = rt * 128;

    const uint32_t* asrc = g_afrag + (size_t)rt * 16384;
    const uint32_t* bbase = g_bfrag + (size_t)ch * 128 * 2048;   // ch*16 tiles * 8 chunks

    // -------- prologue: cp.async A tile (group 0), chunks 0 & 1 --------
#pragma unroll
    for (int i = 0; i < 16; i++) {
        const int ga = i * 256 + tid;
        CP_ASYNC16(sbase + ga * 16, asrc + ga * 4);
    }
    CP_COMMIT();
#pragma unroll
    for (int c = 0; c < 2; c++) {
#pragma unroll
        for (int i = 0; i < 2; i++) {
            const int gi = i * 256 + tid;
            CP_ASYNC16(sbase + (B_OFF + c * B_BUF + gi * 4) * 4,
                       bbase + (size_t)c * 2048 + gi * 4);
        }
        CP_COMMIT();
    }

    float acc[4][4][4];
#pragma unroll
    for (int mf = 0; mf < 4; mf++)
#pragma unroll
        for (int nf = 0; nf < 4; nf++)
#pragma unroll
            for (int c = 0; c < 4; c++) acc[mf][nf][c] = 0.f;

    float runM = -CUDART_INF_F, runS = 0.f;
    int cbuf = 0;                                // buffer of current chunk
    int gc = 0;                                  // global chunk index 0..127

    for (int t = 0; t < TPC; t++) {
        for (int kc = 0; kc < NKC; kc++) {
            // wait until chunk gc is resident (groups complete in order)
            if (gc < NCHUNKT - 2)      CP_WAIT(2);
            else if (gc == NCHUNKT - 2) CP_WAIT(1);
            else                        CP_WAIT(0);
            __syncthreads();           // all warps done with chunk gc-1's buffer

            if (gc + 2 < NCHUNKT) {    // refill that buffer with chunk gc+2
                const int ib = (cbuf + 2 >= 3) ? cbuf - 1 : cbuf + 2;
                const uint32_t* src = bbase + (size_t)(gc + 2) * 2048;
#pragma unroll
                for (int i = 0; i < 2; i++) {
                    const int gi = i * 256 + tid;
                    CP_ASYNC16(sbase + (B_OFF + ib * B_BUF + gi * 4) * 4, src + gi * 4);
                }
                CP_COMMIT();
            }

            // -------- MMA: 2 k16-steps on chunk gc --------
            const uint32_t* Bu = smu + B_OFF + cbuf * B_BUF;
#pragma unroll
            for (int ksl = 0; ksl < 2; ksl++) {
                uint2 bfr[4];
#pragma unroll
                for (int nf = 0; nf < 4; nf++)
                    bfr[nf] = *(const uint2*)(Bu + ((wn * 4 + nf) * 2 + ksl) * 64
                                              + lane * 2);
#pragma unroll
                for (int mf = 0; mf < 4; mf++) {
                    const uint4 af = *(const uint4*)(smu
                        + ((wm * 4 + mf) * 16 + (kc * 2 + ksl)) * 128 + lane * 4);
#pragma unroll
                    for (int nf = 0; nf < 4; nf++)
                        mma_bf16(acc[mf][nf], af.x, af.y, af.z, af.w,
                                 bfr[nf].x, bfr[nf].y);
                }
            }
            cbuf = (cbuf == 2) ? 0 : cbuf + 1;
            gc++;
        }

        // -------- epilogue: fold 128-col sim tile into online (m, s) base-2 --------
        {
            const int c0g = ch * 2048 + t * 128 + wn * 32 + tq * 2;
            float* red = smf + RED_OFF;          // [wn][row][m,s]
            float tm[8], ts[8];
#pragma unroll
            for (int mf = 0; mf < 4; mf++)
#pragma unroll
                for (int hh = 0; hh < 2; hh++) {
                    const int gr = r0 + wm * 64 + mf * 16 + g + hh * 8;
                    float m = -CUDART_INF_F;
#pragma unroll
                    for (int nf = 0; nf < 4; nf++)
#pragma unroll
                        for (int c = 0; c < 2; c++) {
                            float v = acc[mf][nf][hh * 2 + c];
                            if (gr == c0g + nf * 8 + c) v = -CUDART_INF_F;  // self mask
                            acc[mf][nf][hh * 2 + c] = v;
                            m = fmaxf(m, v);
                        }
                    tm[mf * 2 + hh] = m;
                }
#pragma unroll
            for (int s = 0; s < 8; s++) {        // quad reduce (lanes of same row)
                tm[s] = fmaxf(tm[s], __shfl_xor_sync(0xffffffffu, tm[s], 1));
                tm[s] = fmaxf(tm[s], __shfl_xor_sync(0xffffffffu, tm[s], 2));
            }
#pragma unroll
            for (int mf = 0; mf < 4; mf++)
#pragma unroll
                for (int hh = 0; hh < 2; hh++) {
                    float sv = 0.f;
#pragma unroll
                    for (int nf = 0; nf < 4; nf++)
#pragma unroll
                        for (int c = 0; c < 2; c++)
                            sv += ex2f(acc[mf][nf][hh * 2 + c] - tm[mf * 2 + hh]);
                    ts[mf * 2 + hh] = sv;
                }
#pragma unroll
            for (int s = 0; s < 8; s++) {
                ts[s] += __shfl_xor_sync(0xffffffffu, ts[s], 1);
                ts[s] += __shfl_xor_sync(0xffffffffu, ts[s], 2);
            }
            if (tq == 0) {
#pragma unroll
                for (int mf = 0; mf < 4; mf++)
#pragma unroll
                    for (int hh = 0; hh < 2; hh++) {
                        const int row = wm * 64 + mf * 16 + g + hh * 8;
                        red[(wn * 128 + row) * 2 + 0] = tm[mf * 2 + hh];
                        red[(wn * 128 + row) * 2 + 1] = ts[mf * 2 + hh];
                    }
            }
            __syncthreads();
            if (tid < 128) {                     // thread tid owns row r0+tid
                float M = red[tid * 2];
#pragma unroll
                for (int q = 1; q < 4; q++) M = fmaxf(M, red[(q * 128 + tid) * 2]);
                float S = 0.f;
#pragma unroll
                for (int q = 0; q < 4; q++)
                    S += red[(q * 128 + tid) * 2 + 1]
                       * ex2f(red[(q * 128 + tid) * 2] - M);
                const float nm = fmaxf(runM, M);
                runS = runS * ex2f(runM - nm) + S * ex2f(M - nm);
                runM = nm;
            }
            __syncthreads();                     // red reads done before next tile
#pragma unroll
            for (int mf = 0; mf < 4; mf++)
#pragma unroll
                for (int nf = 0; nf < 4; nf++)
#pragma unroll
                    for (int c = 0; c < 4; c++) acc[mf][nf][c] = 0.f;
        }
    }

    if (tid < 128) {
        g_pm[ch][r0 + tid] = runM;               // base-2 max of sim*2*log2e
        g_ps[ch][r0 + tid] = runS;               // base-2 sumexp
    }
}

// ==========================================================================
// Merge 4 column-chunk partials per row (base-2), exact fp32 pos, per-row loss.
// ==========================================================================
__global__ void combine_kernel(const float* __restrict__ hi, const float* __restrict__ hj) {
    const int gwarp = (int)((blockIdx.x * blockDim.x + threadIdx.x) >> 5);
    const int lane = threadIdx.x & 31;
    if (gwarp >= BATCHSZ) return;

    const float* a = hi + (size_t)gwarp * DIM;
    const float* b = hj + (size_t)gwarp * DIM;
    const int k = lane * 8;
    float4 a0 = *(const float4*)(a + k);
    float4 a1 = *(const float4*)(a + k + 4);
    float4 b0 = *(const float4*)(b + k);
    float4 b1 = *(const float4*)(b + k + 4);
    float d = a0.x * b0.x + a0.y * b0.y + a0.z * b0.z + a0.w * b0.w
            + a1.x * b1.x + a1.y * b1.y + a1.z * b1.z + a1.w * b1.w;
#pragma unroll
    for (int off = 16; off > 0; off >>= 1)
        d += __shfl_xor_sync(0xffffffffu, d, off);
    const float pos = d * 2.0f;                  // exact fp32 sim / temp

    if (lane < 2) {
        const int r = gwarp + lane * BATCHSZ;
        float M = g_pm[0][r];
#pragma unroll
        for (int c = 1; c < NCH; c++) M = fmaxf(M, g_pm[c][r]);
        float S = 0.f;
#pragma unroll
        for (int c = 0; c < NCH; c++) S += g_ps[c][r] * ex2f(g_pm[c][r] - M);
        g_lrow[r] = LN2F * (M + __log2f(S)) - pos;   // lse_e - pos
    }
}

// Deterministic single-block reduction -> mean (replay-stable, no atomics).
__global__ void reduce_kernel(float* __restrict__ out) {
    __shared__ float sm[256];
    const int tid = threadIdx.x;
    float s = 0.f;
    for (int i = tid; i < NROWS; i += 256) s += g_lrow[i];
    sm[tid] = s;
    __syncthreads();
    for (int stride = 128; stride > 0; stride >>= 1) {
        if (tid < stride) sm[tid] += sm[tid + stride];
        __syncthreads();
    }
    if (tid == 0) out[0] = sm[0] * (1.0f / NROWS);
}

extern "C" void kernel_launch(void* const* d_in, const int* in_sizes, int n_in,
                              void* d_out, int out_size) {
    const float* hi = (const float*)d_in[0];
    const float* hj = (const float*)d_in[1];
    float* out = (float*)d_out;

    prep_kernel<<<2048, 256>>>(hi, hj);
    cudaFuncSetAttribute(ntxent_mma_kernel,
                         cudaFuncAttributeMaxDynamicSharedMemorySize, SMEM_BYTES);
    ntxent_mma_kernel<<<64 * NCH, 256, SMEM_BYTES>>>();
    combine_kernel<<<(BATCHSZ * 32) / 256, 256>>>(hi, hj);
    reduce_kernel<<<1, 256>>>(out);
}